// round 15
// baseline (speedup 1.0000x reference)
#include <cuda_runtime.h>
#include <stdint.h>

#define DATA_DIM  4096
#define PAIRS     (DATA_DIM / 2)     // 2048
#define QUADS     (DATA_DIM / 4)     // 1024 float4 per row
#define BATCH     16384
#define ROWS_PER  4                  // rows per work item
#define WORK      (BATCH / ROWS_PER) // 4096 work items
#define NBLK      148                // persistent CTAs, 1/SM (192KB smem)
#define TPB       1024
#define MODM      ((unsigned long long)(WORK + NBLK))
#define ROW_END   0x7fffffff
#define DEPTH     3
#define CHUNK_BYTES (ROWS_PER * DATA_DIM * 4)   // 65536: four consecutive rows

// Dynamic smem: 3 x 64KB input buffers + mbarriers.
#define SM_IN(i)   ((i) * 65536)
#define SM_MBAR    196608
#define SMEM_SZ    (196608 + 64)

// Work-stealing counter. Zero at module load; each launch consumes exactly
// WORK real grabs + NBLK terminator grabs (each CTA stops grabbing at its
// first terminator), so the counter advances by exactly MODM per launch and
// item = v % MODM stays valid across graph replays with no reset.
__device__ unsigned long long g_ctr;

__device__ __forceinline__ void mbar_init(uint32_t mbar, uint32_t cnt) {
    asm volatile("mbarrier.init.shared.b64 [%0], %1;" :: "r"(mbar), "r"(cnt) : "memory");
}
__device__ __forceinline__ void mbar_expect_tx(uint32_t mbar, uint32_t bytes) {
    asm volatile("mbarrier.arrive.expect_tx.shared.b64 _, [%0], %1;"
                 :: "r"(mbar), "r"(bytes) : "memory");
}
__device__ __forceinline__ void mbar_wait(uint32_t mbar, uint32_t parity) {
    uint32_t done;
    asm volatile(
        "{\n\t.reg .pred p;\n\t"
        "mbarrier.try_wait.parity.acquire.cta.shared::cta.b64 p, [%1], %2;\n\t"
        "selp.b32 %0, 1, 0, p;\n\t}"
        : "=r"(done) : "r"(mbar), "r"(parity) : "memory");
    if (!done) {
        asm volatile(
            "{\n\t.reg .pred P1;\n\t"
            "W_%=:\n\t"
            "mbarrier.try_wait.parity.acquire.cta.shared::cta.b64 P1, [%0], %1, 0x989680;\n\t"
            "@P1 bra.uni D_%=;\n\t"
            "bra.uni W_%=;\n\t"
            "D_%=:\n\t}"
            :: "r"(mbar), "r"(parity) : "memory");
    }
}
__device__ __forceinline__ void bulk_load_chunk(uint32_t sdst, const void* gsrc, uint32_t mbar) {
    asm volatile(
        "cp.async.bulk.shared::cta.global.mbarrier::complete_tx::bytes [%0], [%1], %2, [%3];"
        :: "r"(sdst), "l"(gsrc), "r"((uint32_t)CHUNK_BYTES), "r"(mbar) : "memory");
}
__device__ __forceinline__ void fence_async() {
    asm volatile("fence.proxy.async.shared::cta;" ::: "memory");
}

// One persistent CTA per SM (1024 threads), depth-3 TMA input ring of 64KB
// chunks (four consecutive rows per transaction -> long contiguous DRAM
// bursts), register gather, direct coalesced STG.128 output, atomic work
// stealing on 4-row work items. Per-SM in-flight read bytes identical to the
// 3x(2x32KB) config; only burst granularity doubles.
__global__ void __launch_bounds__(TPB)
permute_tma4row_kernel(const float* __restrict__ z, const void* __restrict__ perm,
                       float* __restrict__ out) {
    extern __shared__ char smem[];
    __shared__ int s_item[DEPTH];   // work item assigned to each pipeline slot

    const int tid = threadIdx.x;
    const uint32_t sbase = (uint32_t)__cvta_generic_to_shared(smem);

    // ---- Pair-map -> registers. Thread tid owns output quad tid of every
    // row: needs source pairs perm[4*tid]>>1 and perm[4*tid+2]>>1 (same for
    // all rows; row r adds r*PAIRS in smem and r*QUADS in the output).
    // dtype detect: perm[1] is always odd => int32 word[1]!=0; little-endian
    // int64 high word of perm[0] == 0.
    const int* p32 = (const int*)perm;
    const bool is64 = (p32[1] == 0) && (p32[3] == 0) && (p32[5] == 0) && (p32[7] == 0);
    int e0, e1;
    if (is64) {
        e0 = (int)((const long long*)perm)[4 * tid];
        e1 = (int)((const long long*)perm)[4 * tid + 2];
    } else {
        e0 = p32[4 * tid];
        e1 = p32[4 * tid + 2];
    }
    const int sp0 = e0 >> 1;
    const int sp1 = e1 >> 1;

    // ---- Prologue: init mbarriers, steal + issue up to DEPTH chunk loads.
    bool stop = false;   // meaningful in tid0 only
    if (tid == 0) {
        #pragma unroll
        for (int d = 0; d < DEPTH; d++) mbar_init(sbase + SM_MBAR + 8 * d, 1);
        fence_async();
        #pragma unroll
        for (int d = 0; d < DEPTH; d++) {
            int it = ROW_END;
            if (!stop) {
                int v = (int)(atomicAdd(&g_ctr, 1ULL) % MODM);
                if (v < WORK) it = v; else stop = true;
            }
            s_item[d] = it;
            if (it != ROW_END) {
                mbar_expect_tx(sbase + SM_MBAR + 8 * d, CHUNK_BYTES);
                bulk_load_chunk(sbase + SM_IN(d),
                                z + (long long)it * (ROWS_PER * DATA_DIM),
                                sbase + SM_MBAR + 8 * d);
            }
        }
    }
    __syncthreads();

    uint32_t ph[DEPTH] = {0, 0, 0};
    int iter = 0;

    while (true) {
        const int slot = iter % DEPTH;
        const int item = s_item[slot];
        if (item == ROW_END) break;

        // Wait for this slot's TMA load, then gather straight to gmem.
        mbar_wait(sbase + SM_MBAR + 8 * slot, ph[slot]);
        ph[slot] ^= 1;

        {
            const float2* __restrict__ b = (const float2*)(smem + SM_IN(slot));
            float4* __restrict__ o =
                (float4*)(out + (long long)item * (ROWS_PER * DATA_DIM));
            #pragma unroll
            for (int r = 0; r < ROWS_PER; r++) {
                float2 a = b[r * PAIRS + sp0];
                float2 c = b[r * PAIRS + sp1];
                o[r * QUADS + tid] = make_float4(a.x, a.y, c.x, c.y);
            }
        }
        __syncthreads();   // all reads of in[slot] done before refill

        if (tid == 0) {
            int it = ROW_END;
            if (!stop) {
                int v = (int)(atomicAdd(&g_ctr, 1ULL) % MODM);
                if (v < WORK) it = v; else stop = true;
            }
            s_item[slot] = it;
            if (it != ROW_END) {
                mbar_expect_tx(sbase + SM_MBAR + 8 * slot, CHUNK_BYTES);
                bulk_load_chunk(sbase + SM_IN(slot),
                                z + (long long)it * (ROWS_PER * DATA_DIM),
                                sbase + SM_MBAR + 8 * slot);
            }
        }
        iter++;
        __syncthreads();   // s_item[slot] visible before next use of this slot
    }
}

extern "C" void kernel_launch(void* const* d_in, const int* in_sizes, int n_in,
                              void* d_out, int out_size) {
    const float* z    = (const float*)d_in[0];
    const void*  perm = d_in[1];
    float*       out  = (float*)d_out;

    cudaFuncSetAttribute(permute_tma4row_kernel,
                         cudaFuncAttributeMaxDynamicSharedMemorySize, SMEM_SZ);
    permute_tma4row_kernel<<<NBLK, TPB, SMEM_SZ>>>(z, perm, out);
}

// round 16
// speedup vs baseline: 1.2209x; 1.2209x over previous
#include <cuda_runtime.h>
#include <stdint.h>

#define DATA_DIM  4096
#define PAIRS     (DATA_DIM / 2)     // 2048
#define QUADS     (DATA_DIM / 4)     // 1024 float4 per row
#define BATCH     16384
#define WORK      (BATCH / 2)        // 8192 two-row work items
#define NBLK      (148 * 3)          // persistent CTAs, 3/SM (64KB smem each)
#define TPB       256
#define MODM      ((unsigned long long)(WORK + NBLK))
#define ROW_END   0x7fffffff
#define CHUNK_BYTES (2 * DATA_DIM * 4)   // 32768: two consecutive rows

// Dynamic smem: 2 x 32KB input buffers + mbarriers.
#define SM_IN(i)   ((i) * 32768)
#define SM_MBAR    65536
#define SMEM_SZ    (65536 + 64)

// Work-stealing counter. Zero at module load; each launch consumes exactly
// WORK real grabs + NBLK terminator grabs (each CTA stops grabbing at its
// first terminator), so the counter advances by exactly MODM per launch and
// item = v % MODM stays valid across graph replays with no reset.
__device__ unsigned long long g_ctr;

__device__ __forceinline__ void mbar_init(uint32_t mbar, uint32_t cnt) {
    asm volatile("mbarrier.init.shared.b64 [%0], %1;" :: "r"(mbar), "r"(cnt) : "memory");
}
__device__ __forceinline__ void mbar_expect_tx(uint32_t mbar, uint32_t bytes) {
    asm volatile("mbarrier.arrive.expect_tx.shared.b64 _, [%0], %1;"
                 :: "r"(mbar), "r"(bytes) : "memory");
}
__device__ __forceinline__ void mbar_wait(uint32_t mbar, uint32_t parity) {
    uint32_t done;
    asm volatile(
        "{\n\t.reg .pred p;\n\t"
        "mbarrier.try_wait.parity.acquire.cta.shared::cta.b64 p, [%1], %2;\n\t"
        "selp.b32 %0, 1, 0, p;\n\t}"
        : "=r"(done) : "r"(mbar), "r"(parity) : "memory");
    if (!done) {
        asm volatile(
            "{\n\t.reg .pred P1;\n\t"
            "W_%=:\n\t"
            "mbarrier.try_wait.parity.acquire.cta.shared::cta.b64 P1, [%0], %1, 0x989680;\n\t"
            "@P1 bra.uni D_%=;\n\t"
            "bra.uni W_%=;\n\t"
            "D_%=:\n\t}"
            :: "r"(mbar), "r"(parity) : "memory");
    }
}
__device__ __forceinline__ void bulk_load_chunk(uint32_t sdst, const void* gsrc, uint32_t mbar) {
    asm volatile(
        "cp.async.bulk.shared::cta.global.mbarrier::complete_tx::bytes [%0], [%1], %2, [%3];"
        :: "r"(sdst), "l"(gsrc), "r"((uint32_t)CHUNK_BYTES), "r"(mbar) : "memory");
}
// DRAM -> L2 staging prefetch (no smem destination, no completion tracking).
__device__ __forceinline__ void bulk_prefetch_l2(const void* gsrc) {
    asm volatile("cp.async.bulk.prefetch.L2.global [%0], %1;"
                 :: "l"(gsrc), "r"((uint32_t)CHUNK_BYTES) : "memory");
}
__device__ __forceinline__ void fence_async() {
    asm volatile("fence.proxy.async.shared::cta;" ::: "memory");
}

// Persistent CTAs, depth-2 TMA smem ring of 32KB chunks + 1 extra chunk
// staged in L2 via bulk prefetch (effective read depth 3 at zero smem cost).
// Register gather, direct coalesced STG.128 output, atomic work stealing.
__global__ void __launch_bounds__(TPB)
permute_tma_pf_kernel(const float* __restrict__ z, const void* __restrict__ perm,
                      float* __restrict__ out) {
    extern __shared__ char smem[];
    __shared__ int s_item[2];   // work item loaded (or loading) in each slot

    const int tid = threadIdx.x;
    const uint32_t sbase = (uint32_t)__cvta_generic_to_shared(smem);

    // ---- Pair-map -> registers. Quad q needs source pairs perm[4q]>>1 and
    // perm[4q+2]>>1 (identical for both rows of a chunk; row 1 adds a PAIRS
    // offset in smem and a QUADS offset in the output). dtype detect:
    // perm[1] is always odd => int32 word[1]!=0; little-endian int64 high
    // word of perm[0] == 0.
    const int* p32 = (const int*)perm;
    const bool is64 = (p32[1] == 0) && (p32[3] == 0) && (p32[5] == 0) && (p32[7] == 0);
    int2 pq[4];
    #pragma unroll
    for (int k = 0; k < 4; k++) {
        int q = tid + k * TPB;
        int e0, e1;
        if (is64) {
            e0 = (int)((const long long*)perm)[4 * q];
            e1 = (int)((const long long*)perm)[4 * q + 2];
        } else {
            e0 = p32[4 * q];
            e1 = p32[4 * q + 2];
        }
        pq[k] = make_int2(e0 >> 1, e1 >> 1);
    }

    // ---- Prologue (tid0): init mbarriers; steal + load slots 0,1; steal one
    // more item and stage it in L2 (pending).
    bool stop = false;       // tid0 only
    int pending = ROW_END;   // tid0 only: stolen + L2-prefetched, not yet loaded
    if (tid == 0) {
        mbar_init(sbase + SM_MBAR, 1);
        mbar_init(sbase + SM_MBAR + 8, 1);
        fence_async();
        #pragma unroll
        for (int d = 0; d < 2; d++) {
            int it = ROW_END;
            if (!stop) {
                int v = (int)(atomicAdd(&g_ctr, 1ULL) % MODM);
                if (v < WORK) it = v; else stop = true;
            }
            s_item[d] = it;
            if (it != ROW_END) {
                mbar_expect_tx(sbase + SM_MBAR + 8 * d, CHUNK_BYTES);
                bulk_load_chunk(sbase + SM_IN(d),
                                z + (long long)it * (2 * DATA_DIM),
                                sbase + SM_MBAR + 8 * d);
            }
        }
        if (!stop) {
            int v = (int)(atomicAdd(&g_ctr, 1ULL) % MODM);
            if (v < WORK) {
                pending = v;
                bulk_prefetch_l2(z + (long long)v * (2 * DATA_DIM));
            } else stop = true;
        }
    }
    __syncthreads();

    uint32_t ph[2] = {0, 0};
    int iter = 0;

    while (true) {
        const int slot = iter & 1;
        const int item = s_item[slot];
        if (item == ROW_END) break;

        // Wait for this slot's TMA load, then gather straight to gmem.
        mbar_wait(sbase + SM_MBAR + 8 * slot, ph[slot]);
        ph[slot] ^= 1;

        {
            const float2* __restrict__ b = (const float2*)(smem + SM_IN(slot));
            float4* __restrict__ o = (float4*)(out + (long long)item * (2 * DATA_DIM));
            // Row 0 (pairs [0,PAIRS), quads [0,QUADS))
            #pragma unroll
            for (int k = 0; k < 4; k++) {
                int2 p = pq[k];
                float2 a = b[p.x];
                float2 c = b[p.y];
                o[tid + k * TPB] = make_float4(a.x, a.y, c.x, c.y);
            }
            // Row 1 (pairs [PAIRS,2*PAIRS), quads [QUADS,2*QUADS))
            #pragma unroll
            for (int k = 0; k < 4; k++) {
                int2 p = pq[k];
                float2 a = b[PAIRS + p.x];
                float2 c = b[PAIRS + p.y];
                o[QUADS + tid + k * TPB] = make_float4(a.x, a.y, c.x, c.y);
            }
        }
        __syncthreads();   // all reads of in[slot] done before tid0 refills it

        if (tid == 0) {
            // Promote the L2-staged pending item into this slot's smem buffer,
            // then steal + L2-prefetch a fresh item.
            const int p = pending;
            s_item[slot] = p;
            if (p != ROW_END) {
                mbar_expect_tx(sbase + SM_MBAR + 8 * slot, CHUNK_BYTES);
                bulk_load_chunk(sbase + SM_IN(slot),
                                z + (long long)p * (2 * DATA_DIM),
                                sbase + SM_MBAR + 8 * slot);
                pending = ROW_END;
                if (!stop) {
                    int v = (int)(atomicAdd(&g_ctr, 1ULL) % MODM);
                    if (v < WORK) {
                        pending = v;
                        bulk_prefetch_l2(z + (long long)v * (2 * DATA_DIM));
                    } else stop = true;
                }
            }
        }
        iter++;
        // No second barrier needed: s_item[slot] written above is next read at
        // iter+2, which is separated by the next iteration's __syncthreads.
    }
}

extern "C" void kernel_launch(void* const* d_in, const int* in_sizes, int n_in,
                              void* d_out, int out_size) {
    const float* z    = (const float*)d_in[0];
    const void*  perm = d_in[1];
    float*       out  = (float*)d_out;

    cudaFuncSetAttribute(permute_tma_pf_kernel,
                         cudaFuncAttributeMaxDynamicSharedMemorySize, SMEM_SZ);
    permute_tma_pf_kernel<<<NBLK, TPB, SMEM_SZ>>>(z, perm, out);
}

// round 17
// speedup vs baseline: 1.2307x; 1.0080x over previous
#include <cuda_runtime.h>
#include <stdint.h>

#define DATA_DIM  4096
#define PAIRS     (DATA_DIM / 2)     // 2048
#define QUADS     (DATA_DIM / 4)     // 1024 float4 per row
#define BATCH     16384
#define WORK      (BATCH / 2)        // 8192 two-row work items
#define NBLK      (148 * 2)          // persistent CTAs, 2/SM (96KB smem each)
#define TPB       256
#define MODM      ((unsigned long long)(WORK + NBLK))
#define ROW_END   0x7fffffff
#define CHUNK_BYTES (2 * DATA_DIM * 4)   // 32768: two consecutive rows

// Dynamic smem: 2 x 32KB input ring + 1 x 32KB output staging + mbarriers.
#define SM_IN(i)   ((i) * 32768)
#define SM_OUT     65536
#define SM_MBAR    98304
#define SMEM_SZ    (98304 + 64)

// Work-stealing counter. Zero at module load; each launch consumes exactly
// WORK real grabs + NBLK terminator grabs (each CTA stops grabbing at its
// first terminator), so the counter advances by exactly MODM per launch and
// item = v % MODM stays valid across graph replays with no reset.
__device__ unsigned long long g_ctr;

__device__ __forceinline__ void mbar_init(uint32_t mbar, uint32_t cnt) {
    asm volatile("mbarrier.init.shared.b64 [%0], %1;" :: "r"(mbar), "r"(cnt) : "memory");
}
__device__ __forceinline__ void mbar_expect_tx(uint32_t mbar, uint32_t bytes) {
    asm volatile("mbarrier.arrive.expect_tx.shared.b64 _, [%0], %1;"
                 :: "r"(mbar), "r"(bytes) : "memory");
}
__device__ __forceinline__ void mbar_wait(uint32_t mbar, uint32_t parity) {
    uint32_t done;
    asm volatile(
        "{\n\t.reg .pred p;\n\t"
        "mbarrier.try_wait.parity.acquire.cta.shared::cta.b64 p, [%1], %2;\n\t"
        "selp.b32 %0, 1, 0, p;\n\t}"
        : "=r"(done) : "r"(mbar), "r"(parity) : "memory");
    if (!done) {
        asm volatile(
            "{\n\t.reg .pred P1;\n\t"
            "W_%=:\n\t"
            "mbarrier.try_wait.parity.acquire.cta.shared::cta.b64 P1, [%0], %1, 0x989680;\n\t"
            "@P1 bra.uni D_%=;\n\t"
            "bra.uni W_%=;\n\t"
            "D_%=:\n\t}"
            :: "r"(mbar), "r"(parity) : "memory");
    }
}
__device__ __forceinline__ void bulk_load_chunk(uint32_t sdst, const void* gsrc, uint32_t mbar) {
    asm volatile(
        "cp.async.bulk.shared::cta.global.mbarrier::complete_tx::bytes [%0], [%1], %2, [%3];"
        :: "r"(sdst), "l"(gsrc), "r"((uint32_t)CHUNK_BYTES), "r"(mbar) : "memory");
}
__device__ __forceinline__ void bulk_store_chunk(void* gdst, uint32_t ssrc) {
    asm volatile("cp.async.bulk.global.shared::cta.bulk_group [%0], [%1], %2;"
                 :: "l"(gdst), "r"(ssrc), "r"((uint32_t)CHUNK_BYTES) : "memory");
    asm volatile("cp.async.bulk.commit_group;" ::: "memory");
}
// Out buffer reusable once TMA has drained it from smem (not DRAM completion).
__device__ __forceinline__ void bulk_store_wait_read0() {
    asm volatile("cp.async.bulk.wait_group.read 0;" ::: "memory");
}
__device__ __forceinline__ void fence_async() {
    asm volatile("fence.proxy.async.shared::cta;" ::: "memory");
}

// Persistent CTAs (2/SM). Per 2-row work item: one 32KB TMA bulk load in,
// smem gather (random LDS.64 x2 -> conflict-free STS.128) into a 32KB staging
// buffer, one 32KB contiguous TMA bulk store out. 32KB bursts in BOTH
// directions maximize HBM row-buffer locality; atomic work stealing.
__global__ void __launch_bounds__(TPB)
permute_tma_bb_kernel(const float* __restrict__ z, const void* __restrict__ perm,
                      float* __restrict__ out) {
    extern __shared__ char smem[];
    __shared__ int s_item[2];   // work item assigned to each input slot

    const int tid = threadIdx.x;
    const uint32_t sbase = (uint32_t)__cvta_generic_to_shared(smem);

    // ---- Pair-map -> registers. Quad q needs source pairs perm[4q]>>1 and
    // perm[4q+2]>>1 (identical for both rows of a chunk; row 1 adds a PAIRS
    // offset in smem input and a QUADS offset in staging). dtype detect:
    // perm[1] is always odd => int32 word[1]!=0; little-endian int64 high
    // word of perm[0] == 0.
    const int* p32 = (const int*)perm;
    const bool is64 = (p32[1] == 0) && (p32[3] == 0) && (p32[5] == 0) && (p32[7] == 0);
    int2 pq[4];
    #pragma unroll
    for (int k = 0; k < 4; k++) {
        int q = tid + k * TPB;
        int e0, e1;
        if (is64) {
            e0 = (int)((const long long*)perm)[4 * q];
            e1 = (int)((const long long*)perm)[4 * q + 2];
        } else {
            e0 = p32[4 * q];
            e1 = p32[4 * q + 2];
        }
        pq[k] = make_int2(e0 >> 1, e1 >> 1);
    }

    // ---- Prologue: init mbarriers, steal + issue 2 chunk loads.
    bool stop = false;   // tid0 only
    if (tid == 0) {
        mbar_init(sbase + SM_MBAR, 1);
        mbar_init(sbase + SM_MBAR + 8, 1);
        fence_async();
        #pragma unroll
        for (int d = 0; d < 2; d++) {
            int it = ROW_END;
            if (!stop) {
                int v = (int)(atomicAdd(&g_ctr, 1ULL) % MODM);
                if (v < WORK) it = v; else stop = true;
            }
            s_item[d] = it;
            if (it != ROW_END) {
                mbar_expect_tx(sbase + SM_MBAR + 8 * d, CHUNK_BYTES);
                bulk_load_chunk(sbase + SM_IN(d),
                                z + (long long)it * (2 * DATA_DIM),
                                sbase + SM_MBAR + 8 * d);
            }
        }
    }
    __syncthreads();

    uint32_t ph[2] = {0, 0};
    int iter = 0;

    while (true) {
        const int slot = iter & 1;
        const int item = s_item[slot];
        if (item == ROW_END) break;

        // Wait for this slot's TMA load; free the staging buffer (the store
        // issued last iteration has long drained 32KB from smem).
        mbar_wait(sbase + SM_MBAR + 8 * slot, ph[slot]);
        ph[slot] ^= 1;
        if (tid == 0) bulk_store_wait_read0();
        __syncthreads();   // staging free, input visible, to all threads

        // Gather in[slot] -> staging (random LDS.64 x2, conflict-free STS.128).
        {
            const float2* __restrict__ b = (const float2*)(smem + SM_IN(slot));
            float4* __restrict__ o = (float4*)(smem + SM_OUT);
            // Row 0 (pairs [0,PAIRS), quads [0,QUADS))
            #pragma unroll
            for (int k = 0; k < 4; k++) {
                int2 p = pq[k];
                float2 a = b[p.x];
                float2 c = b[p.y];
                o[tid + k * TPB] = make_float4(a.x, a.y, c.x, c.y);
            }
            // Row 1 (pairs [PAIRS,2*PAIRS), quads [QUADS,2*QUADS))
            #pragma unroll
            for (int k = 0; k < 4; k++) {
                int2 p = pq[k];
                float2 a = b[PAIRS + p.x];
                float2 c = b[PAIRS + p.y];
                o[QUADS + tid + k * TPB] = make_float4(a.x, a.y, c.x, c.y);
            }
        }
        __syncthreads();   // staging filled; all reads of in[slot] done

        if (tid == 0) {
            // One contiguous 32KB bulk store of the permuted chunk.
            fence_async();
            bulk_store_chunk(out + (long long)item * (2 * DATA_DIM), sbase + SM_OUT);
            // Refill this input slot with a freshly stolen item.
            int it = ROW_END;
            if (!stop) {
                int v = (int)(atomicAdd(&g_ctr, 1ULL) % MODM);
                if (v < WORK) it = v; else stop = true;
            }
            s_item[slot] = it;
            if (it != ROW_END) {
                mbar_expect_tx(sbase + SM_MBAR + 8 * slot, CHUNK_BYTES);
                bulk_load_chunk(sbase + SM_IN(slot),
                                z + (long long)it * (2 * DATA_DIM),
                                sbase + SM_MBAR + 8 * slot);
            }
        }
        iter++;
        // s_item[slot] written above is next read at iter+2; the barriers of
        // iter+1 separate the write from that read.
    }

    // Drain the final outstanding store before exit.
    if (tid == 0) bulk_store_wait_read0();
}

extern "C" void kernel_launch(void* const* d_in, const int* in_sizes, int n_in,
                              void* d_out, int out_size) {
    const float* z    = (const float*)d_in[0];
    const void*  perm = d_in[1];
    float*       out  = (float*)d_out;

    cudaFuncSetAttribute(permute_tma_bb_kernel,
                         cudaFuncAttributeMaxDynamicSharedMemorySize, SMEM_SZ);
    permute_tma_bb_kernel<<<NBLK, TPB, SMEM_SZ>>>(z, perm, out);
}